// round 14
// baseline (speedup 1.0000x reference)
#include <cuda_runtime.h>
#include <cuda_bf16.h>
#include <stdint.h>
#include <math.h>

// Problem constants
#define BB 128
#define TT 2048
#define FF 80
#define NCLS 10
#define HH 32
#define MROWS (BB*TT)          // 262144
#define EPSBN 1e-5f

typedef unsigned long long ull;

// ---------------- scratch (static __device__ arrays; no allocation) -------
__device__ float g_y1[(size_t)MROWS * 256];
__device__ float g_y2[(size_t)MROWS * 128];
__device__ float g_y3[(size_t)MROWS * 64];
__device__ float g_xpf[(size_t)MROWS * 96];
__device__ float g_xpb[(size_t)MROWS * 96];
__device__ float g_gru[(size_t)MROWS * 64];
__device__ float g_scores[(size_t)MROWS];
__device__ float g_pooled[BB * 64];
__device__ float g_sums1[512];
__device__ float g_sums2[256];
__device__ float g_sums3[128];
// pre-converted weights: uint2 {hi-bf16x2, lo-bf16x2} per k-pair
__device__ uint2 g_w1c[256 * 40];
__device__ uint2 g_w2c[128 * 128];
__device__ uint2 g_w3c[64 * 64];
__device__ uint2 g_wifc[96 * 32];
__device__ uint2 g_wibc[96 * 32];
__device__ uint2 g_wa1c[32 * 32];

// ---------------- helpers ----------------------------------------------------
__device__ __forceinline__ uint32_t pack_bf2(float x, float y) {
    unsigned short h0 = __bfloat16_as_ushort(__float2bfloat16_rn(x));
    unsigned short h1 = __bfloat16_as_ushort(__float2bfloat16_rn(y));
    return (uint32_t)h0 | ((uint32_t)h1 << 16);
}

// truncation hi/lo split: hi = top16 bits (exact residual), lo = bf16(v - hi)
__device__ __forceinline__ void split2(float2 v, uint32_t& hi, uint32_t& lo) {
    uint32_t bx = __float_as_uint(v.x) & 0xffff0000u;
    uint32_t by = __float_as_uint(v.y) & 0xffff0000u;
    hi = (bx >> 16) | by;
    lo = pack_bf2(v.x - __uint_as_float(bx), v.y - __uint_as_float(by));
}

__device__ __forceinline__ void mma_bf16(float* c, const uint32_t* a, const uint32_t* b) {
    asm volatile(
        "mma.sync.aligned.m16n8k16.row.col.f32.bf16.bf16.f32 "
        "{%0,%1,%2,%3}, {%4,%5,%6,%7}, {%8,%9}, {%0,%1,%2,%3};"
        : "+f"(c[0]), "+f"(c[1]), "+f"(c[2]), "+f"(c[3])
        : "r"(a[0]), "r"(a[1]), "r"(a[2]), "r"(a[3]), "r"(b[0]), "r"(b[1]));
}

__device__ __forceinline__ void packf2(ull& d, float lo, float hi) {
    asm("mov.b64 %0, {%1, %2};" : "=l"(d) : "f"(lo), "f"(hi));
}
__device__ __forceinline__ float sumf2(ull v) {
    float lo, hi;
    asm("mov.b64 {%0, %1}, %2;" : "=f"(lo), "=f"(hi) : "l"(v));
    return lo + hi;
}
__device__ __forceinline__ void fma2(ull& d, ull a, ull b) {
    asm("fma.rn.f32x2 %0, %1, %2, %0;" : "+l"(d) : "l"(a), "l"(b));
}
__device__ __forceinline__ float tanh_ap(float x) {
    float y;
    asm("tanh.approx.f32 %0, %1;" : "=f"(y) : "f"(x));
    return y;
}
__device__ __forceinline__ float sigmoid_ap(float x) {
    return fmaf(tanh_ap(0.5f * x), 0.5f, 0.5f);
}

__device__ __forceinline__ uint2 conv_pair(float2 v) {
    uint32_t hi, lo;
    split2(v, hi, lo);
    return make_uint2(hi, lo);
}

// ---------------- prep: zero stats + convert all weights (one launch) -------
#define NP1 10240
#define NP2 16384
#define NP3 4096
#define NPF 3072
#define NPB 3072
#define NPA 1024
#define NPTOT (NP1+NP2+NP3+NPF+NPB+NPA)   // 37888

__global__ void prep_kernel(
    const float* __restrict__ W1, const float* __restrict__ W2,
    const float* __restrict__ W3, const float* __restrict__ Wif,
    const float* __restrict__ Wib, const float* __restrict__ Wa1,
    uint2* w1c, uint2* w2c, uint2* w3c, uint2* wifc, uint2* wibc, uint2* wa1c,
    float* s1, float* s2, float* s3)
{
    int tid = threadIdx.x;
    if (blockIdx.x == 0) {
        if (tid < 512) s1[tid] = 0.f;
        if (tid < 256) s2[tid] = 0.f;
        if (tid < 128) s3[tid] = 0.f;
    }
    for (int p = blockIdx.x * 256 + tid; p < NPTOT; p += gridDim.x * 256) {
        int q = p;
        if (q < NP1) { w1c[q] = conv_pair(((const float2*)W1)[q]); continue; }
        q -= NP1;
        if (q < NP2) { w2c[q] = conv_pair(((const float2*)W2)[q]); continue; }
        q -= NP2;
        if (q < NP3) { w3c[q] = conv_pair(((const float2*)W3)[q]); continue; }
        q -= NP3;
        if (q < NPF) { wifc[q] = conv_pair(((const float2*)Wif)[q]); continue; }
        q -= NPF;
        if (q < NPB) { wibc[q] = conv_pair(((const float2*)Wib)[q]); continue; }
        q -= NPB;
        wa1c[q] = conv_pair(((const float2*)Wa1)[q]);
    }
}

// =====================================================================
// BGEMM (tensor-core, bf16 hi/lo split): C = f(A) @ W^T + bias
// Fragment-owner staging (R13). DO_T: BN affine in-kernel. DO_SCORE: N=32
// scores. DUAL: blockIdx.y selects weight/bias/output set B.
// =====================================================================
template<int DO_T, int DO_STATS, int NARROW, int DO_SCORE, int DUAL>
__global__ __launch_bounds__(256, 2) void bgemm_kernel(
    const float* __restrict__ A, const uint2* __restrict__ Whl0,
    const float* __restrict__ bias0,
    const float* __restrict__ stats, const float* __restrict__ gamma,
    const float* __restrict__ beta, float invM,
    const float* __restrict__ wa2,
    float* __restrict__ C0, float* __restrict__ sums,
    const uint2* __restrict__ Whl1, const float* __restrict__ bias1,
    float* __restrict__ C1,
    int M, int N, int K)
{
    __shared__ __align__(16) uint32_t sAh[2][8][32][4];
    __shared__ __align__(16) uint32_t sAl[2][8][32][4];
    __shared__ __align__(16) uint32_t sBh[2][16][32][2];
    __shared__ __align__(16) uint32_t sBl[2][16][32][2];
    __shared__ float s_sum[128], s_sq[128];
    __shared__ __align__(8) float s_scale[256], s_shift[256];

    const int tid = threadIdx.x;
    const int lane = tid & 31;
    const int wid = tid >> 5;
    const int wm = NARROW ? wid : (wid & 3);
    const int wn = NARROW ? 0 : (wid >> 2);
    const int MT = NARROW ? 1 : 2;
    const int NT = DO_SCORE ? 4 : 8;
    const int bm0 = blockIdx.x * 128;
    const int bn0 = DUAL ? 0 : blockIdx.y * 128;
    const int l4 = lane >> 2;
    const int ln = lane & 3;

    const uint2* Whl = (DUAL && blockIdx.y) ? Whl1 : Whl0;
    const float* bias = (DUAL && blockIdx.y) ? bias1 : bias0;
    float* C = (DUAL && blockIdx.y) ? C1 : C0;

    if (DO_STATS && tid < 128) { s_sum[tid] = 0.f; s_sq[tid] = 0.f; }
    if (DO_T && tid < K) {
        float m = stats[tid] * invM;
        float v = stats[K + tid] * invM - m * m;
        float sc = gamma[tid] * rsqrtf(v + EPSBN);
        s_scale[tid] = sc;
        s_shift[tid] = beta[tid] - m * sc;
    }
    __syncthreads();

    // ---- staging ownership ----
    const int K2 = K >> 1;
    const size_t rA = (size_t)(bm0 + wid * 16 + l4);
    const float2* Ap0 = (const float2*)A + rA * K2 + ln;
    const float2* Ap1 = Ap0 + (size_t)8 * K2;

    const int NSLOT = NARROW ? 1 : 2;
    int ntB[2];
    const uint2* Wp[2];
    bool wokB[2];
#pragma unroll
    for (int s = 0; s < NSLOT; s++) {
        ntB[s] = NARROW ? wid : (wid * 2 + s);
        int n = bn0 + ntB[s] * 8 + l4;
        wokB[s] = (n < N);
        Wp[s] = wokB[s] ? (Whl + (size_t)n * K2 + ln) : Whl;
    }

    float acc[2][8][4];
#pragma unroll
    for (int mt = 0; mt < 2; mt++)
#pragma unroll
        for (int nt = 0; nt < 8; nt++)
#pragma unroll
            for (int q = 0; q < 4; q++) acc[mt][nt][q] = 0.f;

    const int nch = K >> 4;

    float2 a00, a10, a01, a11;
    uint2 wb[2][2];

    // ---- load chunk 0 into regs ----
    {
        a00 = Ap0[0];  a01 = Ap0[4];
        a10 = Ap1[0];  a11 = Ap1[4];
        if (DO_T) {
            float2 sc0 = ((const float2*)s_scale)[ln];
            float2 sh0 = ((const float2*)s_shift)[ln];
            float2 sc1 = ((const float2*)s_scale)[ln + 4];
            float2 sh1 = ((const float2*)s_shift)[ln + 4];
            a00.x = fmaxf(fmaf(a00.x, sc0.x, sh0.x), 0.f);
            a00.y = fmaxf(fmaf(a00.y, sc0.y, sh0.y), 0.f);
            a10.x = fmaxf(fmaf(a10.x, sc0.x, sh0.x), 0.f);
            a10.y = fmaxf(fmaf(a10.y, sc0.y, sh0.y), 0.f);
            a01.x = fmaxf(fmaf(a01.x, sc1.x, sh1.x), 0.f);
            a01.y = fmaxf(fmaf(a01.y, sc1.y, sh1.y), 0.f);
            a11.x = fmaxf(fmaf(a11.x, sc1.x, sh1.x), 0.f);
            a11.y = fmaxf(fmaf(a11.y, sc1.y, sh1.y), 0.f);
        }
#pragma unroll
        for (int s = 0; s < NSLOT; s++) {
            wb[s][0] = wokB[s] ? Wp[s][0] : make_uint2(0u, 0u);
            wb[s][1] = wokB[s] ? Wp[s][4] : make_uint2(0u, 0u);
        }
    }
    {
        uint32_t h0, l0, h1, l1, h2, l2, h3, l3;
        split2(a00, h0, l0); split2(a10, h1, l1);
        split2(a01, h2, l2); split2(a11, h3, l3);
        *(uint4*)&sAh[0][wid][lane][0] = make_uint4(h0, h1, h2, h3);
        *(uint4*)&sAl[0][wid][lane][0] = make_uint4(l0, l1, l2, l3);
#pragma unroll
        for (int s = 0; s < NSLOT; s++) {
            *(uint2*)&sBh[0][ntB[s]][lane][0] = make_uint2(wb[s][0].x, wb[s][1].x);
            *(uint2*)&sBl[0][ntB[s]][lane][0] = make_uint2(wb[s][0].y, wb[s][1].y);
        }
    }
    __syncthreads();

    for (int s = 0; s < nch; s++) {
        const int cur = s & 1;
        const int kq2 = (s + 1) << 3;

        if (s + 1 < nch) {
            a00 = Ap0[kq2];     a01 = Ap0[kq2 + 4];
            a10 = Ap1[kq2];     a11 = Ap1[kq2 + 4];
            if (DO_T) {
                float2 sc0 = ((const float2*)s_scale)[kq2 + ln];
                float2 sh0 = ((const float2*)s_shift)[kq2 + ln];
                float2 sc1 = ((const float2*)s_scale)[kq2 + ln + 4];
                float2 sh1 = ((const float2*)s_shift)[kq2 + ln + 4];
                a00.x = fmaxf(fmaf(a00.x, sc0.x, sh0.x), 0.f);
                a00.y = fmaxf(fmaf(a00.y, sc0.y, sh0.y), 0.f);
                a10.x = fmaxf(fmaf(a10.x, sc0.x, sh0.x), 0.f);
                a10.y = fmaxf(fmaf(a10.y, sc0.y, sh0.y), 0.f);
                a01.x = fmaxf(fmaf(a01.x, sc1.x, sh1.x), 0.f);
                a01.y = fmaxf(fmaf(a01.y, sc1.y, sh1.y), 0.f);
                a11.x = fmaxf(fmaf(a11.x, sc1.x, sh1.x), 0.f);
                a11.y = fmaxf(fmaf(a11.y, sc1.y, sh1.y), 0.f);
            }
#pragma unroll
            for (int t = 0; t < NSLOT; t++) {
                wb[t][0] = wokB[t] ? Wp[t][kq2] : make_uint2(0u, 0u);
                wb[t][1] = wokB[t] ? Wp[t][kq2 + 4] : make_uint2(0u, 0u);
            }
        }

        // ---- MMA on current buffer ----
        {
            uint32_t ah[2][4], al[2][4];
#pragma unroll
            for (int mt = 0; mt < MT; mt++) {
                const int mtile = NARROW ? wm : (wm * 2 + mt);
                uint4 t0 = *(const uint4*)&sAh[cur][mtile][lane][0];
                ah[mt][0] = t0.x; ah[mt][1] = t0.y; ah[mt][2] = t0.z; ah[mt][3] = t0.w;
                uint4 t1 = *(const uint4*)&sAl[cur][mtile][lane][0];
                al[mt][0] = t1.x; al[mt][1] = t1.y; al[mt][2] = t1.z; al[mt][3] = t1.w;
            }
#pragma unroll
            for (int nt = 0; nt < NT; nt++) {
                uint2 bh2 = *(const uint2*)&sBh[cur][wn * 8 + nt][lane][0];
                uint2 bl2 = *(const uint2*)&sBl[cur][wn * 8 + nt][lane][0];
                uint32_t bh[2] = {bh2.x, bh2.y};
                uint32_t bl[2] = {bl2.x, bl2.y};
#pragma unroll
                for (int mt = 0; mt < MT; mt++) {
                    mma_bf16(acc[mt][nt], ah[mt], bh);
                    mma_bf16(acc[mt][nt], ah[mt], bl);
                    mma_bf16(acc[mt][nt], al[mt], bh);
                }
            }
        }

        if (s + 1 < nch) {
            const int nxt = cur ^ 1;
            uint32_t h0, l0, h1, l1, h2, l2, h3, l3;
            split2(a00, h0, l0); split2(a10, h1, l1);
            split2(a01, h2, l2); split2(a11, h3, l3);
            *(uint4*)&sAh[nxt][wid][lane][0] = make_uint4(h0, h1, h2, h3);
            *(uint4*)&sAl[nxt][wid][lane][0] = make_uint4(l0, l1, l2, l3);
#pragma unroll
            for (int t = 0; t < NSLOT; t++) {
                *(uint2*)&sBh[nxt][ntB[t]][lane][0] = make_uint2(wb[t][0].x, wb[t][1].x);
                *(uint2*)&sBl[nxt][ntB[t]][lane][0] = make_uint2(wb[t][0].y, wb[t][1].y);
            }
            __syncthreads();
        }
    }

    if (DO_SCORE) {
        float s0 = 0.f, s1 = 0.f;
#pragma unroll
        for (int nt = 0; nt < 4; nt++) {
            const int col = nt * 8 + ln * 2;
            float b0 = bias[col], b1 = bias[col + 1];
            float w0 = wa2[col], w1 = wa2[col + 1];
            s0 += tanhf(acc[0][nt][0] + b0) * w0 + tanhf(acc[0][nt][1] + b1) * w1;
            s1 += tanhf(acc[0][nt][2] + b0) * w0 + tanhf(acc[0][nt][3] + b1) * w1;
        }
        s0 += __shfl_xor_sync(0xffffffffu, s0, 1);
        s0 += __shfl_xor_sync(0xffffffffu, s0, 2);
        s1 += __shfl_xor_sync(0xffffffffu, s1, 1);
        s1 += __shfl_xor_sync(0xffffffffu, s1, 2);
        if (ln == 0) {
            C[bm0 + wm * 16 + l4]     = s0;
            C[bm0 + wm * 16 + l4 + 8] = s1;
        }
        return;
    }

    // ---- normal epilogue ----
#pragma unroll
    for (int nt = 0; nt < 8; nt++) {
        const int colb = wn * 64 + nt * 8 + ln * 2;
        const int col = bn0 + colb;
        const bool ok = (col < N);
        float b0 = ok ? bias[col] : 0.f;
        float b1 = ok ? bias[col + 1] : 0.f;
        float cs0 = 0.f, cs1 = 0.f, cq0 = 0.f, cq1 = 0.f;
#pragma unroll
        for (int mt = 0; mt < MT; mt++) {
            float c0 = acc[mt][nt][0] + b0;
            float c1 = acc[mt][nt][1] + b1;
            float c2 = acc[mt][nt][2] + b0;
            float c3 = acc[mt][nt][3] + b1;
            const int row = bm0 + (NARROW ? wm * 16 : wm * 32 + mt * 16) + l4;
            if (ok) {
                *(float2*)(C + (size_t)row * N + col)       = make_float2(c0, c1);
                *(float2*)(C + (size_t)(row + 8) * N + col) = make_float2(c2, c3);
            }
            if (DO_STATS) {
                cs0 += c0 + c2; cs1 += c1 + c3;
                cq0 += c0 * c0 + c2 * c2; cq1 += c1 * c1 + c3 * c3;
            }
        }
        if (DO_STATS) {
#pragma unroll
            for (int o = 4; o < 32; o <<= 1) {
                cs0 += __shfl_xor_sync(0xffffffffu, cs0, o);
                cs1 += __shfl_xor_sync(0xffffffffu, cs1, o);
                cq0 += __shfl_xor_sync(0xffffffffu, cq0, o);
                cq1 += __shfl_xor_sync(0xffffffffu, cq1, o);
            }
            if (l4 == 0) {
                atomicAdd(&s_sum[colb], cs0);
                atomicAdd(&s_sum[colb + 1], cs1);
                atomicAdd(&s_sq[colb], cq0);
                atomicAdd(&s_sq[colb + 1], cq1);
            }
        }
    }

    if (DO_STATS) {
        __syncthreads();
        if (tid < 128) {
            int n = bn0 + tid;
            if (n < N) {
                atomicAdd(&sums[n],     s_sum[tid]);
                atomicAdd(&sums[N + n], s_sq[tid]);
            }
        }
    }
}

// ---------------- GRU recurrence (one warp per (batch, direction)) ----------
// R11 structure with DEPTH-8 static prefetch (flat arrays + register-copy
// rotation; no runtime buffer index -> no local-memory demotion).
__global__ __launch_bounds__(32) void gru_kernel(
    const float* __restrict__ xp_f, const float* __restrict__ xp_b,
    const float* __restrict__ Whh_f, const float* __restrict__ bhh_f,
    const float* __restrict__ Whh_b, const float* __restrict__ bhh_b,
    float* __restrict__ gru_out)
{
    int b = blockIdx.x;
    int dir = blockIdx.y;
    int j = threadIdx.x;

    const float* xp  = dir ? xp_b  : xp_f;
    const float* Whh = dir ? Whh_b : Whh_f;
    const float* bhh = dir ? bhh_b : bhh_f;

    ull Wr2[16], Wz2[16], Wn2[16];
#pragma unroll
    for (int k2 = 0; k2 < 16; k2++) {
        packf2(Wr2[k2], Whh[j * 32 + 2 * k2],        Whh[j * 32 + 2 * k2 + 1]);
        packf2(Wz2[k2], Whh[(32 + j) * 32 + 2 * k2], Whh[(32 + j) * 32 + 2 * k2 + 1]);
        packf2(Wn2[k2], Whh[(64 + j) * 32 + 2 * k2], Whh[(64 + j) * 32 + 2 * k2 + 1]);
    }
    float br = bhh[j], bz = bhh[32 + j], bnn = bhh[64 + j];

    float h = 0.f;
    const int st = dir ? -96 : 96;
    int tcur = dir ? (TT - 1) : 0;
    const float* cur = xp + (size_t)b * TT * 96 + (size_t)tcur * 96;
    const float* pf = cur + 8 * st;
    float* outp = gru_out + ((size_t)b * TT + tcur) * 64 + dir * 32 + j;
    const long ost = dir ? -64 : 64;

    float fr[8], fz[8], fn[8];
#pragma unroll
    for (int q = 0; q < 8; q++) {
        const float* p = cur + q * st;
        fr[q] = p[j]; fz[q] = p[32 + j]; fn[q] = p[64 + j];
    }

    for (int it = 0; it < TT; it += 8) {
        float nfr[8], nfz[8], nfn[8];
        const bool more = (it + 8 < TT);
        if (more) {
#pragma unroll
            for (int q = 0; q < 8; q++) {
                const float* p = pf + q * st;
                nfr[q] = p[j]; nfz[q] = p[32 + j]; nfn[q] = p[64 + j];
            }
        }
        pf += 8 * st;

#pragma unroll
        for (int u = 0; u < 8; u++) {
            ull ra = 0ull, rb = 0ull;
            ull za = 0ull, zb = 0ull;
            ull na = 0ull, nb = 0ull;
#pragma unroll
            for (int k2 = 0; k2 < 16; k2++) {
                float h0 = __shfl_sync(0xffffffffu, h, 2 * k2);
                float h1 = __shfl_sync(0xffffffffu, h, 2 * k2 + 1);
                ull hp;
                packf2(hp, h0, h1);
                if (k2 & 1) {
                    fma2(rb, Wr2[k2], hp);
                    fma2(zb, Wz2[k2], hp);
                    fma2(nb, Wn2[k2], hp);
                } else {
                    fma2(ra, Wr2[k2], hp);
                    fma2(za, Wz2[k2], hp);
                    fma2(na, Wn2[k2], hp);
                }
            }
            float accr = br + sumf2(ra) + sumf2(rb);
            float accz = bz + sumf2(za) + sumf2(zb);
            float accn = bnn + sumf2(na) + sumf2(nb);
            float r = sigmoid_ap(fr[u] + accr);
            float z = sigmoid_ap(fz[u] + accz);
            float n = tanh_ap(fmaf(r, accn, fn[u]));
            h = fmaf(z, h - n, n);
            *outp = h;
            outp += ost;
        }
#pragma unroll
        for (int q = 0; q < 8; q++) { fr[q] = nfr[q]; fz[q] = nfz[q]; fn[q] = nfn[q]; }
    }
}

// ---------------- softmax + pooling (scores precomputed) --------------------
__global__ __launch_bounds__(256) void attn_kernel(
    const float* __restrict__ gru,
    const float* __restrict__ scores,
    float* __restrict__ pooled)
{
    __shared__ float s_scores[TT];
    __shared__ float s_red[8];
    __shared__ float s_bcast[2];
    __shared__ float s_pool[4][64];

    int b = blockIdx.x;
    int tid = threadIdx.x;
    int lane = tid & 31;
    int w = tid >> 5;

    const float* sb = scores + (size_t)b * TT;
    for (int t = tid; t < TT; t += 256) s_scores[t] = sb[t];
    __syncthreads();

    float m = -1e30f;
    for (int t = tid; t < TT; t += 256) m = fmaxf(m, s_scores[t]);
#pragma unroll
    for (int o = 16; o; o >>= 1) m = fmaxf(m, __shfl_xor_sync(0xffffffffu, m, o));
    if (lane == 0) s_red[w] = m;
    __syncthreads();
    if (tid == 0) {
        float mm = s_red[0];
#pragma unroll
        for (int i = 1; i < 8; i++) mm = fmaxf(mm, s_red[i]);
        s_bcast[0] = mm;
    }
    __syncthreads();
    m = s_bcast[0];

    float sum = 0.f;
    for (int t = tid; t < TT; t += 256) {
        float e = __expf(s_scores[t] - m);
        s_scores[t] = e;
        sum += e;
    }
#pragma unroll
    for (int o = 16; o; o >>= 1) sum += __shfl_xor_sync(0xffffffffu, sum, o);
    if (lane == 0) s_red[w] = sum;
    __syncthreads();
    if (tid == 0) {
        float ss = 0.f;
#pragma unroll
        for (int i = 0; i < 8; i++) ss += s_red[i];
        s_bcast[1] = ss;
    }
    __syncthreads();
    float sumexp = s_bcast[1];

    const float* gb = gru + (size_t)b * TT * 64;
    int c = tid & 63;
    int grp = tid >> 6;
    float acc = 0.f;
    for (int t = grp; t < TT; t += 4) acc += s_scores[t] * gb[(size_t)t * 64 + c];
    s_pool[grp][c] = acc;
    __syncthreads();
    if (tid < 64) {
        float tot = s_pool[0][tid] + s_pool[1][tid] + s_pool[2][tid] + s_pool[3][tid];
        pooled[b * 64 + tid] = tot / sumexp;
    }
}

// ---------------- classifier -------------------------------------------------
__global__ __launch_bounds__(128) void cls_kernel(
    const float* __restrict__ pooled,
    const float* __restrict__ Wc1, const float* __restrict__ bc1,
    const float* __restrict__ gc, const float* __restrict__ bec,
    const float* __restrict__ Wc2, const float* __restrict__ bc2,
    float* __restrict__ out)
{
    __shared__ float s_sum[32], s_sq[32], s_scale[32], s_shift[32];
    int r = threadIdx.x;
    if (r < 32) { s_sum[r] = 0.f; s_sq[r] = 0.f; }
    __syncthreads();

    float x[64];
#pragma unroll
    for (int k = 0; k < 64; k++) x[k] = pooled[r * 64 + k];

    float q[32];
#pragma unroll
    for (int u = 0; u < 32; u++) {
        float a = bc1[u];
#pragma unroll
        for (int k = 0; k < 64; k++) a += Wc1[u * 64 + k] * x[k];
        q[u] = a;
        atomicAdd(&s_sum[u], a);
        atomicAdd(&s_sq[u], a * a);
    }
    __syncthreads();
    if (r < 32) {
        float m = s_sum[r] * (1.f / 128.f);
        float v = s_sq[r] * (1.f / 128.f) - m * m;
        float sc = gc[r] * rsqrtf(v + EPSBN);
        s_scale[r] = sc;
        s_shift[r] = bec[r] - m * sc;
    }
    __syncthreads();

    float qn[32];
#pragma unroll
    for (int u = 0; u < 32; u++) {
        float t = q[u] * s_scale[u] + s_shift[u];
        qn[u] = t > 0.f ? t : 0.f;
    }
#pragma unroll
    for (int c = 0; c < NCLS; c++) {
        float a = bc2[c];
#pragma unroll
        for (int k = 0; k < 32; k++) a += Wc2[c * 32 + k] * qn[k];
        out[r * NCLS + c] = a;
    }
}

// ---------------- launch ----------------------------------------------------
extern "C" void kernel_launch(void* const* d_in, const int* in_sizes, int n_in,
                              void* d_out, int out_size)
{
    (void)in_sizes; (void)n_in; (void)out_size;

    const float* x     = (const float*)d_in[0];
    const float* W1    = (const float*)d_in[1];
    const float* b1    = (const float*)d_in[2];
    const float* g1    = (const float*)d_in[3];
    const float* be1   = (const float*)d_in[4];
    const float* W2    = (const float*)d_in[5];
    const float* b2    = (const float*)d_in[6];
    const float* g2    = (const float*)d_in[7];
    const float* be2   = (const float*)d_in[8];
    const float* W3    = (const float*)d_in[9];
    const float* b3    = (const float*)d_in[10];
    const float* g3    = (const float*)d_in[11];
    const float* be3   = (const float*)d_in[12];
    const float* Wih_f = (const float*)d_in[13];
    const float* Whh_f = (const float*)d_in[14];
    const float* bih_f = (const float*)d_in[15];
    const float* bhh_f = (const float*)d_in[16];
    const float* Wih_b = (const float*)d_in[17];
    const float* Whh_b = (const float*)d_in[18];
    const float* bih_b = (const float*)d_in[19];
    const float* bhh_b = (const float*)d_in[20];
    const float* Wa1   = (const float*)d_in[21];
    const float* ba1   = (const float*)d_in[22];
    const float* Wa2   = (const float*)d_in[23];
    const float* ba2   = (const float*)d_in[24];  (void)ba2;  // softmax-invariant
    const float* Wc1   = (const float*)d_in[25];
    const float* bc1   = (const float*)d_in[26];
    const float* gc    = (const float*)d_in[27];
    const float* bec   = (const float*)d_in[28];
    const float* Wc2   = (const float*)d_in[29];
    const float* bc2   = (const float*)d_in[30];
    float* out = (float*)d_out;

    float *y1, *y2, *y3, *xpf, *xpb, *gru, *scores, *pooled;
    float *sums1, *sums2, *sums3;
    uint2 *w1c, *w2c, *w3c, *wifc, *wibc, *wa1c;
    cudaGetSymbolAddress((void**)&y1, g_y1);
    cudaGetSymbolAddress((void**)&y2, g_y2);
    cudaGetSymbolAddress((void**)&y3, g_y3);
    cudaGetSymbolAddress((void**)&xpf, g_xpf);
    cudaGetSymbolAddress((void**)&xpb, g_xpb);
    cudaGetSymbolAddress((void**)&gru, g_gru);
    cudaGetSymbolAddress((void**)&scores, g_scores);
    cudaGetSymbolAddress((void**)&pooled, g_pooled);
    cudaGetSymbolAddress((void**)&sums1, g_sums1);
    cudaGetSymbolAddress((void**)&sums2, g_sums2);
    cudaGetSymbolAddress((void**)&sums3, g_sums3);
    cudaGetSymbolAddress((void**)&w1c, g_w1c);
    cudaGetSymbolAddress((void**)&w2c, g_w2c);
    cudaGetSymbolAddress((void**)&w3c, g_w3c);
    cudaGetSymbolAddress((void**)&wifc, g_wifc);
    cudaGetSymbolAddress((void**)&wibc, g_wibc);
    cudaGetSymbolAddress((void**)&wa1c, g_wa1c);

    const float invM = 1.f / (float)MROWS;
    const int gx = MROWS / 128;

    // 0: prep (zero stats + all weight conversions)
    prep_kernel<<<148, 256>>>(W1, W2, W3, Wih_f, Wih_b, Wa1,
                              w1c, w2c, w3c, wifc, wibc, wa1c,
                              sums1, sums2, sums3);

    // 1: L1 (N=256, K=80) + stats
    bgemm_kernel<0,1,0,0,0><<<dim3(gx, 2), 256>>>(
        x, w1c, b1, nullptr, nullptr, nullptr, 0.f, nullptr,
        y1, sums1, nullptr, nullptr, nullptr, MROWS, 256, FF);

    // 2: L2 (N=128, K=256), BN1 affine in-kernel
    bgemm_kernel<1,1,0,0,0><<<dim3(gx, 1), 256>>>(
        y1, w2c, b2, sums1, g1, be1, invM, nullptr,
        y2, sums2, nullptr, nullptr, nullptr, MROWS, 128, 256);

    // 3: L3 (N=64, K=128) NARROW, BN2 affine in-kernel
    bgemm_kernel<1,1,1,0,0><<<dim3(gx, 1), 256>>>(
        y2, w3c, b3, sums2, g2, be2, invM, nullptr,
        y3, sums3, nullptr, nullptr, nullptr, MROWS, 64, 128);

    // 4: xp fused f+b (N=96, K=64), BN3 affine in-kernel
    bgemm_kernel<1,0,0,0,1><<<dim3(gx, 2), 256>>>(
        y3, wifc, bih_f, sums3, g3, be3, invM, nullptr,
        xpf, nullptr, wibc, bih_b, xpb, MROWS, 96, 64);

    // 5: GRU recurrence (R11 geometry, depth-8 static prefetch)
    gru_kernel<<<dim3(BB, 2), 32>>>(xpf, xpb, Whh_f, bhh_f, Whh_b, bhh_b, gru);

    // 6: attention scores (N=32, K=64, NARROW+SCORE)
    bgemm_kernel<0,0,1,1,0><<<dim3(gx, 1), 256>>>(
        gru, wa1c, ba1, nullptr, nullptr, nullptr, 0.f, Wa2,
        scores, nullptr, nullptr, nullptr, nullptr, MROWS, 32, 64);

    // 7: softmax + pooling
    attn_kernel<<<BB, 256>>>(gru, scores, pooled);

    // 8: classifier
    cls_kernel<<<1, 128>>>(pooled, Wc1, bc1, gc, bec, Wc2, bc2, out);
}

// round 15
// speedup vs baseline: 1.0415x; 1.0415x over previous
#include <cuda_runtime.h>
#include <cuda_bf16.h>
#include <stdint.h>
#include <math.h>

// Problem constants
#define BB 128
#define TT 2048
#define FF 80
#define NCLS 10
#define HH 32
#define MROWS (BB*TT)          // 262144
#define EPSBN 1e-5f

typedef unsigned long long ull;

// ---------------- scratch (static __device__ arrays; no allocation) -------
__device__ float g_y1[(size_t)MROWS * 256];
__device__ float g_y2[(size_t)MROWS * 128];
__device__ float g_y3[(size_t)MROWS * 64];
__device__ float g_xpf[(size_t)MROWS * 96];
__device__ float g_xpb[(size_t)MROWS * 96];
__device__ float g_gru[(size_t)MROWS * 64];
__device__ float g_scores[(size_t)MROWS];
__device__ float g_pooled[BB * 64];
__device__ float g_sums1[512];
__device__ float g_sums2[256];
__device__ float g_sums3[128];
// pre-converted weights: uint2 {hi-bf16x2, lo-bf16x2} per k-pair
__device__ uint2 g_w1c[256 * 40];
__device__ uint2 g_w2c[128 * 128];
__device__ uint2 g_w3c[64 * 64];
__device__ uint2 g_wifc[96 * 32];
__device__ uint2 g_wibc[96 * 32];
__device__ uint2 g_wa1c[32 * 32];

// ---------------- helpers ----------------------------------------------------
__device__ __forceinline__ uint32_t pack_bf2(float x, float y) {
    unsigned short h0 = __bfloat16_as_ushort(__float2bfloat16_rn(x));
    unsigned short h1 = __bfloat16_as_ushort(__float2bfloat16_rn(y));
    return (uint32_t)h0 | ((uint32_t)h1 << 16);
}

// truncation hi/lo split: hi = top16 bits (exact residual), lo = bf16(v - hi)
__device__ __forceinline__ void split2(float2 v, uint32_t& hi, uint32_t& lo) {
    uint32_t bx = __float_as_uint(v.x) & 0xffff0000u;
    uint32_t by = __float_as_uint(v.y) & 0xffff0000u;
    hi = (bx >> 16) | by;
    lo = pack_bf2(v.x - __uint_as_float(bx), v.y - __uint_as_float(by));
}

__device__ __forceinline__ void mma_bf16(float* c, const uint32_t* a, const uint32_t* b) {
    asm volatile(
        "mma.sync.aligned.m16n8k16.row.col.f32.bf16.bf16.f32 "
        "{%0,%1,%2,%3}, {%4,%5,%6,%7}, {%8,%9}, {%0,%1,%2,%3};"
        : "+f"(c[0]), "+f"(c[1]), "+f"(c[2]), "+f"(c[3])
        : "r"(a[0]), "r"(a[1]), "r"(a[2]), "r"(a[3]), "r"(b[0]), "r"(b[1]));
}

__device__ __forceinline__ void packf2(ull& d, float lo, float hi) {
    asm("mov.b64 %0, {%1, %2};" : "=l"(d) : "f"(lo), "f"(hi));
}
__device__ __forceinline__ float sumf2(ull v) {
    float lo, hi;
    asm("mov.b64 {%0, %1}, %2;" : "=f"(lo), "=f"(hi) : "l"(v));
    return lo + hi;
}
__device__ __forceinline__ void fma2(ull& d, ull a, ull b) {
    asm("fma.rn.f32x2 %0, %1, %2, %0;" : "+l"(d) : "l"(a), "l"(b));
}
__device__ __forceinline__ float tanh_ap(float x) {
    float y;
    asm("tanh.approx.f32 %0, %1;" : "=f"(y) : "f"(x));
    return y;
}
__device__ __forceinline__ float sigmoid_ap(float x) {
    return fmaf(tanh_ap(0.5f * x), 0.5f, 0.5f);
}

__device__ __forceinline__ uint2 conv_pair(float2 v) {
    uint32_t hi, lo;
    split2(v, hi, lo);
    return make_uint2(hi, lo);
}

// ---------------- prep: zero stats + convert all weights (one launch) -------
#define NP1 10240
#define NP2 16384
#define NP3 4096
#define NPF 3072
#define NPB 3072
#define NPA 1024
#define NPTOT (NP1+NP2+NP3+NPF+NPB+NPA)   // 37888

__global__ void prep_kernel(
    const float* __restrict__ W1, const float* __restrict__ W2,
    const float* __restrict__ W3, const float* __restrict__ Wif,
    const float* __restrict__ Wib, const float* __restrict__ Wa1,
    uint2* w1c, uint2* w2c, uint2* w3c, uint2* wifc, uint2* wibc, uint2* wa1c,
    float* s1, float* s2, float* s3)
{
    int tid = threadIdx.x;
    if (blockIdx.x == 0) {
        if (tid < 512) s1[tid] = 0.f;
        if (tid < 256) s2[tid] = 0.f;
        if (tid < 128) s3[tid] = 0.f;
    }
    for (int p = blockIdx.x * 256 + tid; p < NPTOT; p += gridDim.x * 256) {
        int q = p;
        if (q < NP1) { w1c[q] = conv_pair(((const float2*)W1)[q]); continue; }
        q -= NP1;
        if (q < NP2) { w2c[q] = conv_pair(((const float2*)W2)[q]); continue; }
        q -= NP2;
        if (q < NP3) { w3c[q] = conv_pair(((const float2*)W3)[q]); continue; }
        q -= NP3;
        if (q < NPF) { wifc[q] = conv_pair(((const float2*)Wif)[q]); continue; }
        q -= NPF;
        if (q < NPB) { wibc[q] = conv_pair(((const float2*)Wib)[q]); continue; }
        q -= NPB;
        wa1c[q] = conv_pair(((const float2*)Wa1)[q]);
    }
}

// =====================================================================
// BGEMM (tensor-core, bf16 hi/lo split): C = f(A) @ W^T + bias
// Fragment-owner staging (R13). Accumulators sized [MT][NT] by template;
// NARROW variants get 3 blocks/SM via launch_bounds.
// =====================================================================
template<int DO_T, int DO_STATS, int NARROW, int DO_SCORE, int DUAL>
__global__ __launch_bounds__(256, 2 + NARROW) void bgemm_kernel(
    const float* __restrict__ A, const uint2* __restrict__ Whl0,
    const float* __restrict__ bias0,
    const float* __restrict__ stats, const float* __restrict__ gamma,
    const float* __restrict__ beta, float invM,
    const float* __restrict__ wa2,
    float* __restrict__ C0, float* __restrict__ sums,
    const uint2* __restrict__ Whl1, const float* __restrict__ bias1,
    float* __restrict__ C1,
    int M, int N, int K)
{
    __shared__ __align__(16) uint32_t sAh[2][8][32][4];
    __shared__ __align__(16) uint32_t sAl[2][8][32][4];
    __shared__ __align__(16) uint32_t sBh[2][16][32][2];
    __shared__ __align__(16) uint32_t sBl[2][16][32][2];
    __shared__ float s_sum[128], s_sq[128];
    __shared__ __align__(8) float s_scale[256], s_shift[256];

    const int tid = threadIdx.x;
    const int lane = tid & 31;
    const int wid = tid >> 5;
    const int wm = NARROW ? wid : (wid & 3);
    const int wn = NARROW ? 0 : (wid >> 2);
    const int MT = NARROW ? 1 : 2;
    const int NT = DO_SCORE ? 4 : 8;
    const int bm0 = blockIdx.x * 128;
    const int bn0 = DUAL ? 0 : blockIdx.y * 128;
    const int l4 = lane >> 2;
    const int ln = lane & 3;

    const uint2* Whl = (DUAL && blockIdx.y) ? Whl1 : Whl0;
    const float* bias = (DUAL && blockIdx.y) ? bias1 : bias0;
    float* C = (DUAL && blockIdx.y) ? C1 : C0;

    if (DO_STATS && tid < 128) { s_sum[tid] = 0.f; s_sq[tid] = 0.f; }
    if (DO_T && tid < K) {
        float m = stats[tid] * invM;
        float v = stats[K + tid] * invM - m * m;
        float sc = gamma[tid] * rsqrtf(v + EPSBN);
        s_scale[tid] = sc;
        s_shift[tid] = beta[tid] - m * sc;
    }
    __syncthreads();

    // ---- staging ownership ----
    const int K2 = K >> 1;
    const size_t rA = (size_t)(bm0 + wid * 16 + l4);
    const float2* Ap0 = (const float2*)A + rA * K2 + ln;
    const float2* Ap1 = Ap0 + (size_t)8 * K2;

    const int NSLOT = NARROW ? 1 : 2;
    int ntB[2];
    const uint2* Wp[2];
    bool wokB[2];
#pragma unroll
    for (int s = 0; s < NSLOT; s++) {
        ntB[s] = NARROW ? wid : (wid * 2 + s);
        int n = bn0 + ntB[s] * 8 + l4;
        wokB[s] = (n < N);
        Wp[s] = wokB[s] ? (Whl + (size_t)n * K2 + ln) : Whl;
    }

    float acc[NARROW ? 1 : 2][DO_SCORE ? 4 : 8][4];
#pragma unroll
    for (int mt = 0; mt < MT; mt++)
#pragma unroll
        for (int nt = 0; nt < NT; nt++)
#pragma unroll
            for (int q = 0; q < 4; q++) acc[mt][nt][q] = 0.f;

    const int nch = K >> 4;

    float2 a00, a10, a01, a11;
    uint2 wb[2][2];

    // ---- load chunk 0 into regs ----
    {
        a00 = Ap0[0];  a01 = Ap0[4];
        a10 = Ap1[0];  a11 = Ap1[4];
        if (DO_T) {
            float2 sc0 = ((const float2*)s_scale)[ln];
            float2 sh0 = ((const float2*)s_shift)[ln];
            float2 sc1 = ((const float2*)s_scale)[ln + 4];
            float2 sh1 = ((const float2*)s_shift)[ln + 4];
            a00.x = fmaxf(fmaf(a00.x, sc0.x, sh0.x), 0.f);
            a00.y = fmaxf(fmaf(a00.y, sc0.y, sh0.y), 0.f);
            a10.x = fmaxf(fmaf(a10.x, sc0.x, sh0.x), 0.f);
            a10.y = fmaxf(fmaf(a10.y, sc0.y, sh0.y), 0.f);
            a01.x = fmaxf(fmaf(a01.x, sc1.x, sh1.x), 0.f);
            a01.y = fmaxf(fmaf(a01.y, sc1.y, sh1.y), 0.f);
            a11.x = fmaxf(fmaf(a11.x, sc1.x, sh1.x), 0.f);
            a11.y = fmaxf(fmaf(a11.y, sc1.y, sh1.y), 0.f);
        }
#pragma unroll
        for (int s = 0; s < NSLOT; s++) {
            wb[s][0] = wokB[s] ? Wp[s][0] : make_uint2(0u, 0u);
            wb[s][1] = wokB[s] ? Wp[s][4] : make_uint2(0u, 0u);
        }
    }
    {
        uint32_t h0, l0, h1, l1, h2, l2, h3, l3;
        split2(a00, h0, l0); split2(a10, h1, l1);
        split2(a01, h2, l2); split2(a11, h3, l3);
        *(uint4*)&sAh[0][wid][lane][0] = make_uint4(h0, h1, h2, h3);
        *(uint4*)&sAl[0][wid][lane][0] = make_uint4(l0, l1, l2, l3);
#pragma unroll
        for (int s = 0; s < NSLOT; s++) {
            *(uint2*)&sBh[0][ntB[s]][lane][0] = make_uint2(wb[s][0].x, wb[s][1].x);
            *(uint2*)&sBl[0][ntB[s]][lane][0] = make_uint2(wb[s][0].y, wb[s][1].y);
        }
    }
    __syncthreads();

    for (int s = 0; s < nch; s++) {
        const int cur = s & 1;
        const int kq2 = (s + 1) << 3;

        if (s + 1 < nch) {
            a00 = Ap0[kq2];     a01 = Ap0[kq2 + 4];
            a10 = Ap1[kq2];     a11 = Ap1[kq2 + 4];
            if (DO_T) {
                float2 sc0 = ((const float2*)s_scale)[kq2 + ln];
                float2 sh0 = ((const float2*)s_shift)[kq2 + ln];
                float2 sc1 = ((const float2*)s_scale)[kq2 + ln + 4];
                float2 sh1 = ((const float2*)s_shift)[kq2 + ln + 4];
                a00.x = fmaxf(fmaf(a00.x, sc0.x, sh0.x), 0.f);
                a00.y = fmaxf(fmaf(a00.y, sc0.y, sh0.y), 0.f);
                a10.x = fmaxf(fmaf(a10.x, sc0.x, sh0.x), 0.f);
                a10.y = fmaxf(fmaf(a10.y, sc0.y, sh0.y), 0.f);
                a01.x = fmaxf(fmaf(a01.x, sc1.x, sh1.x), 0.f);
                a01.y = fmaxf(fmaf(a01.y, sc1.y, sh1.y), 0.f);
                a11.x = fmaxf(fmaf(a11.x, sc1.x, sh1.x), 0.f);
                a11.y = fmaxf(fmaf(a11.y, sc1.y, sh1.y), 0.f);
            }
#pragma unroll
            for (int t = 0; t < NSLOT; t++) {
                wb[t][0] = wokB[t] ? Wp[t][kq2] : make_uint2(0u, 0u);
                wb[t][1] = wokB[t] ? Wp[t][kq2 + 4] : make_uint2(0u, 0u);
            }
        }

        // ---- MMA on current buffer ----
        {
            uint32_t ah[2][4], al[2][4];
#pragma unroll
            for (int mt = 0; mt < MT; mt++) {
                const int mtile = NARROW ? wm : (wm * 2 + mt);
                uint4 t0 = *(const uint4*)&sAh[cur][mtile][lane][0];
                ah[mt][0] = t0.x; ah[mt][1] = t0.y; ah[mt][2] = t0.z; ah[mt][3] = t0.w;
                uint4 t1 = *(const uint4*)&sAl[cur][mtile][lane][0];
                al[mt][0] = t1.x; al[mt][1] = t1.y; al[mt][2] = t1.z; al[mt][3] = t1.w;
            }
#pragma unroll
            for (int nt = 0; nt < NT; nt++) {
                uint2 bh2 = *(const uint2*)&sBh[cur][wn * 8 + nt][lane][0];
                uint2 bl2 = *(const uint2*)&sBl[cur][wn * 8 + nt][lane][0];
                uint32_t bh[2] = {bh2.x, bh2.y};
                uint32_t bl[2] = {bl2.x, bl2.y};
#pragma unroll
                for (int mt = 0; mt < MT; mt++) {
                    mma_bf16(acc[mt][nt], ah[mt], bh);
                    mma_bf16(acc[mt][nt], ah[mt], bl);
                    mma_bf16(acc[mt][nt], al[mt], bh);
                }
            }
        }

        if (s + 1 < nch) {
            const int nxt = cur ^ 1;
            uint32_t h0, l0, h1, l1, h2, l2, h3, l3;
            split2(a00, h0, l0); split2(a10, h1, l1);
            split2(a01, h2, l2); split2(a11, h3, l3);
            *(uint4*)&sAh[nxt][wid][lane][0] = make_uint4(h0, h1, h2, h3);
            *(uint4*)&sAl[nxt][wid][lane][0] = make_uint4(l0, l1, l2, l3);
#pragma unroll
            for (int t = 0; t < NSLOT; t++) {
                *(uint2*)&sBh[nxt][ntB[t]][lane][0] = make_uint2(wb[t][0].x, wb[t][1].x);
                *(uint2*)&sBl[nxt][ntB[t]][lane][0] = make_uint2(wb[t][0].y, wb[t][1].y);
            }
            __syncthreads();
        }
    }

    if (DO_SCORE) {
        float s0 = 0.f, s1 = 0.f;
#pragma unroll
        for (int nt = 0; nt < 4; nt++) {
            const int col = nt * 8 + ln * 2;
            float b0 = bias[col], b1 = bias[col + 1];
            float w0 = wa2[col], w1 = wa2[col + 1];
            s0 += tanhf(acc[0][nt][0] + b0) * w0 + tanhf(acc[0][nt][1] + b1) * w1;
            s1 += tanhf(acc[0][nt][2] + b0) * w0 + tanhf(acc[0][nt][3] + b1) * w1;
        }
        s0 += __shfl_xor_sync(0xffffffffu, s0, 1);
        s0 += __shfl_xor_sync(0xffffffffu, s0, 2);
        s1 += __shfl_xor_sync(0xffffffffu, s1, 1);
        s1 += __shfl_xor_sync(0xffffffffu, s1, 2);
        if (ln == 0) {
            C[bm0 + wm * 16 + l4]     = s0;
            C[bm0 + wm * 16 + l4 + 8] = s1;
        }
        return;
    }

    // ---- normal epilogue ----
#pragma unroll
    for (int nt = 0; nt < NT; nt++) {
        const int colb = wn * 64 + nt * 8 + ln * 2;
        const int col = bn0 + colb;
        const bool ok = (col < N);
        float b0 = ok ? bias[col] : 0.f;
        float b1 = ok ? bias[col + 1] : 0.f;
        float cs0 = 0.f, cs1 = 0.f, cq0 = 0.f, cq1 = 0.f;
#pragma unroll
        for (int mt = 0; mt < MT; mt++) {
            float c0 = acc[mt][nt][0] + b0;
            float c1 = acc[mt][nt][1] + b1;
            float c2 = acc[mt][nt][2] + b0;
            float c3 = acc[mt][nt][3] + b1;
            const int row = bm0 + (NARROW ? wm * 16 : wm * 32 + mt * 16) + l4;
            if (ok) {
                *(float2*)(C + (size_t)row * N + col)       = make_float2(c0, c1);
                *(float2*)(C + (size_t)(row + 8) * N + col) = make_float2(c2, c3);
            }
            if (DO_STATS) {
                cs0 += c0 + c2; cs1 += c1 + c3;
                cq0 += c0 * c0 + c2 * c2; cq1 += c1 * c1 + c3 * c3;
            }
        }
        if (DO_STATS) {
#pragma unroll
            for (int o = 4; o < 32; o <<= 1) {
                cs0 += __shfl_xor_sync(0xffffffffu, cs0, o);
                cs1 += __shfl_xor_sync(0xffffffffu, cs1, o);
                cq0 += __shfl_xor_sync(0xffffffffu, cq0, o);
                cq1 += __shfl_xor_sync(0xffffffffu, cq1, o);
            }
            if (l4 == 0) {
                atomicAdd(&s_sum[colb], cs0);
                atomicAdd(&s_sum[colb + 1], cs1);
                atomicAdd(&s_sq[colb], cq0);
                atomicAdd(&s_sq[colb + 1], cq1);
            }
        }
    }

    if (DO_STATS) {
        __syncthreads();
        if (tid < 128) {
            int n = bn0 + tid;
            if (n < N) {
                atomicAdd(&sums[n],     s_sum[tid]);
                atomicAdd(&sums[N + n], s_sq[tid]);
            }
        }
    }
}

// ---------------- GRU recurrence (one warp per (batch, direction)) ----------
// FROZEN R11/R13 form: depth-4 static prefetch + shfl h-broadcast + f32x2
// matvec + tanh.approx. 256 single-warp blocks.
__global__ __launch_bounds__(32) void gru_kernel(
    const float* __restrict__ xp_f, const float* __restrict__ xp_b,
    const float* __restrict__ Whh_f, const float* __restrict__ bhh_f,
    const float* __restrict__ Whh_b, const float* __restrict__ bhh_b,
    float* __restrict__ gru_out)
{
    int b = blockIdx.x;
    int dir = blockIdx.y;
    int j = threadIdx.x;

    const float* xp  = dir ? xp_b  : xp_f;
    const float* Whh = dir ? Whh_b : Whh_f;
    const float* bhh = dir ? bhh_b : bhh_f;

    ull Wr2[16], Wz2[16], Wn2[16];
#pragma unroll
    for (int k2 = 0; k2 < 16; k2++) {
        packf2(Wr2[k2], Whh[j * 32 + 2 * k2],        Whh[j * 32 + 2 * k2 + 1]);
        packf2(Wz2[k2], Whh[(32 + j) * 32 + 2 * k2], Whh[(32 + j) * 32 + 2 * k2 + 1]);
        packf2(Wn2[k2], Whh[(64 + j) * 32 + 2 * k2], Whh[(64 + j) * 32 + 2 * k2 + 1]);
    }
    float br = bhh[j], bz = bhh[32 + j], bnn = bhh[64 + j];

    float h = 0.f;
    const int st = dir ? -96 : 96;
    int tcur = dir ? (TT - 1) : 0;
    const float* cur = xp + (size_t)b * TT * 96 + (size_t)tcur * 96;
    const float* pf = cur + 4 * st;
    float* outp = gru_out + ((size_t)b * TT + tcur) * 64 + dir * 32 + j;
    const long ost = dir ? -64 : 64;

    float fr[4], fz[4], fn[4];
#pragma unroll
    for (int q = 0; q < 4; q++) {
        const float* p = cur + q * st;
        fr[q] = p[j]; fz[q] = p[32 + j]; fn[q] = p[64 + j];
    }

    for (int it = 0; it < TT; it += 4) {
        float nfr[4], nfz[4], nfn[4];
        const bool more = (it + 4 < TT);
        if (more) {
#pragma unroll
            for (int q = 0; q < 4; q++) {
                const float* p = pf + q * st;
                nfr[q] = p[j]; nfz[q] = p[32 + j]; nfn[q] = p[64 + j];
            }
        }
        pf += 4 * st;

#pragma unroll
        for (int u = 0; u < 4; u++) {
            ull ra = 0ull, rb = 0ull;
            ull za = 0ull, zb = 0ull;
            ull na = 0ull, nb = 0ull;
#pragma unroll
            for (int k2 = 0; k2 < 16; k2++) {
                float h0 = __shfl_sync(0xffffffffu, h, 2 * k2);
                float h1 = __shfl_sync(0xffffffffu, h, 2 * k2 + 1);
                ull hp;
                packf2(hp, h0, h1);
                if (k2 & 1) {
                    fma2(rb, Wr2[k2], hp);
                    fma2(zb, Wz2[k2], hp);
                    fma2(nb, Wn2[k2], hp);
                } else {
                    fma2(ra, Wr2[k2], hp);
                    fma2(za, Wz2[k2], hp);
                    fma2(na, Wn2[k2], hp);
                }
            }
            float accr = br + sumf2(ra) + sumf2(rb);
            float accz = bz + sumf2(za) + sumf2(zb);
            float accn = bnn + sumf2(na) + sumf2(nb);
            float r = sigmoid_ap(fr[u] + accr);
            float z = sigmoid_ap(fz[u] + accz);
            float n = tanh_ap(fmaf(r, accn, fn[u]));
            h = fmaf(z, h - n, n);
            *outp = h;
            outp += ost;
        }
#pragma unroll
        for (int q = 0; q < 4; q++) { fr[q] = nfr[q]; fz[q] = nfz[q]; fn[q] = nfn[q]; }
    }
}

// ---------------- softmax + pooling (scores precomputed) --------------------
__global__ __launch_bounds__(256) void attn_kernel(
    const float* __restrict__ gru,
    const float* __restrict__ scores,
    float* __restrict__ pooled)
{
    __shared__ float s_scores[TT];
    __shared__ float s_red[8];
    __shared__ float s_bcast[2];
    __shared__ float s_pool[4][64];

    int b = blockIdx.x;
    int tid = threadIdx.x;
    int lane = tid & 31;
    int w = tid >> 5;

    const float* sb = scores + (size_t)b * TT;
    for (int t = tid; t < TT; t += 256) s_scores[t] = sb[t];
    __syncthreads();

    float m = -1e30f;
    for (int t = tid; t < TT; t += 256) m = fmaxf(m, s_scores[t]);
#pragma unroll
    for (int o = 16; o; o >>= 1) m = fmaxf(m, __shfl_xor_sync(0xffffffffu, m, o));
    if (lane == 0) s_red[w] = m;
    __syncthreads();
    if (tid == 0) {
        float mm = s_red[0];
#pragma unroll
        for (int i = 1; i < 8; i++) mm = fmaxf(mm, s_red[i]);
        s_bcast[0] = mm;
    }
    __syncthreads();
    m = s_bcast[0];

    float sum = 0.f;
    for (int t = tid; t < TT; t += 256) {
        float e = __expf(s_scores[t] - m);
        s_scores[t] = e;
        sum += e;
    }
#pragma unroll
    for (int o = 16; o; o >>= 1) sum += __shfl_xor_sync(0xffffffffu, sum, o);
    if (lane == 0) s_red[w] = sum;
    __syncthreads();
    if (tid == 0) {
        float ss = 0.f;
#pragma unroll
        for (int i = 0; i < 8; i++) ss += s_red[i];
        s_bcast[1] = ss;
    }
    __syncthreads();
    float sumexp = s_bcast[1];

    const float* gb = gru + (size_t)b * TT * 64;
    int c = tid & 63;
    int grp = tid >> 6;
    float acc = 0.f;
    for (int t = grp; t < TT; t += 4) acc += s_scores[t] * gb[(size_t)t * 64 + c];
    s_pool[grp][c] = acc;
    __syncthreads();
    if (tid < 64) {
        float tot = s_pool[0][tid] + s_pool[1][tid] + s_pool[2][tid] + s_pool[3][tid];
        pooled[b * 64 + tid] = tot / sumexp;
    }
}

// ---------------- classifier -------------------------------------------------
__global__ __launch_bounds__(128) void cls_kernel(
    const float* __restrict__ pooled,
    const float* __restrict__ Wc1, const float* __restrict__ bc1,
    const float* __restrict__ gc, const float* __restrict__ bec,
    const float* __restrict__ Wc2, const float* __restrict__ bc2,
    float* __restrict__ out)
{
    __shared__ float s_sum[32], s_sq[32], s_scale[32], s_shift[32];
    int r = threadIdx.x;
    if (r < 32) { s_sum[r] = 0.f; s_sq[r] = 0.f; }
    __syncthreads();

    float x[64];
#pragma unroll
    for (int k = 0; k < 64; k++) x[k] = pooled[r * 64 + k];

    float q[32];
#pragma unroll
    for (int u = 0; u < 32; u++) {
        float a = bc1[u];
#pragma unroll
        for (int k = 0; k < 64; k++) a += Wc1[u * 64 + k] * x[k];
        q[u] = a;
        atomicAdd(&s_sum[u], a);
        atomicAdd(&s_sq[u], a * a);
    }
    __syncthreads();
    if (r < 32) {
        float m = s_sum[r] * (1.f / 128.f);
        float v = s_sq[r] * (1.f / 128.f) - m * m;
        float sc = gc[r] * rsqrtf(v + EPSBN);
        s_scale[r] = sc;
        s_shift[r] = bec[r] - m * sc;
    }
    __syncthreads();

    float qn[32];
#pragma unroll
    for (int u = 0; u < 32; u++) {
        float t = q[u] * s_scale[u] + s_shift[u];
        qn[u] = t > 0.f ? t : 0.f;
    }
#pragma unroll
    for (int c = 0; c < NCLS; c++) {
        float a = bc2[c];
#pragma unroll
        for (int k = 0; k < 32; k++) a += Wc2[c * 32 + k] * qn[k];
        out[r * NCLS + c] = a;
    }
}

// ---------------- launch ----------------------------------------------------
extern "C" void kernel_launch(void* const* d_in, const int* in_sizes, int n_in,
                              void* d_out, int out_size)
{
    (void)in_sizes; (void)n_in; (void)out_size;

    const float* x     = (const float*)d_in[0];
    const float* W1    = (const float*)d_in[1];
    const float* b1    = (const float*)d_in[2];
    const float* g1    = (const float*)d_in[3];
    const float* be1   = (const float*)d_in[4];
    const float* W2    = (const float*)d_in[5];
    const float* b2    = (const float*)d_in[6];
    const float* g2    = (const float*)d_in[7];
    const float* be2   = (const float*)d_in[8];
    const float* W3    = (const float*)d_in[9];
    const float* b3    = (const float*)d_in[10];
    const float* g3    = (const float*)d_in[11];
    const float* be3   = (const float*)d_in[12];
    const float* Wih_f = (const float*)d_in[13];
    const float* Whh_f = (const float*)d_in[14];
    const float* bih_f = (const float*)d_in[15];
    const float* bhh_f = (const float*)d_in[16];
    const float* Wih_b = (const float*)d_in[17];
    const float* Whh_b = (const float*)d_in[18];
    const float* bih_b = (const float*)d_in[19];
    const float* bhh_b = (const float*)d_in[20];
    const float* Wa1   = (const float*)d_in[21];
    const float* ba1   = (const float*)d_in[22];
    const float* Wa2   = (const float*)d_in[23];
    const float* ba2   = (const float*)d_in[24];  (void)ba2;  // softmax-invariant
    const float* Wc1   = (const float*)d_in[25];
    const float* bc1   = (const float*)d_in[26];
    const float* gc    = (const float*)d_in[27];
    const float* bec   = (const float*)d_in[28];
    const float* Wc2   = (const float*)d_in[29];
    const float* bc2   = (const float*)d_in[30];
    float* out = (float*)d_out;

    float *y1, *y2, *y3, *xpf, *xpb, *gru, *scores, *pooled;
    float *sums1, *sums2, *sums3;
    uint2 *w1c, *w2c, *w3c, *wifc, *wibc, *wa1c;
    cudaGetSymbolAddress((void**)&y1, g_y1);
    cudaGetSymbolAddress((void**)&y2, g_y2);
    cudaGetSymbolAddress((void**)&y3, g_y3);
    cudaGetSymbolAddress((void**)&xpf, g_xpf);
    cudaGetSymbolAddress((void**)&xpb, g_xpb);
    cudaGetSymbolAddress((void**)&gru, g_gru);
    cudaGetSymbolAddress((void**)&scores, g_scores);
    cudaGetSymbolAddress((void**)&pooled, g_pooled);
    cudaGetSymbolAddress((void**)&sums1, g_sums1);
    cudaGetSymbolAddress((void**)&sums2, g_sums2);
    cudaGetSymbolAddress((void**)&sums3, g_sums3);
    cudaGetSymbolAddress((void**)&w1c, g_w1c);
    cudaGetSymbolAddress((void**)&w2c, g_w2c);
    cudaGetSymbolAddress((void**)&w3c, g_w3c);
    cudaGetSymbolAddress((void**)&wifc, g_wifc);
    cudaGetSymbolAddress((void**)&wibc, g_wibc);
    cudaGetSymbolAddress((void**)&wa1c, g_wa1c);

    const float invM = 1.f / (float)MROWS;
    const int gx = MROWS / 128;

    // 0: prep (zero stats + all weight conversions)
    prep_kernel<<<148, 256>>>(W1, W2, W3, Wih_f, Wih_b, Wa1,
                              w1c, w2c, w3c, wifc, wibc, wa1c,
                              sums1, sums2, sums3);

    // 1: L1 (N=256, K=80) + stats
    bgemm_kernel<0,1,0,0,0><<<dim3(gx, 2), 256>>>(
        x, w1c, b1, nullptr, nullptr, nullptr, 0.f, nullptr,
        y1, sums1, nullptr, nullptr, nullptr, MROWS, 256, FF);

    // 2: L2 (N=128, K=256), BN1 affine in-kernel
    bgemm_kernel<1,1,0,0,0><<<dim3(gx, 1), 256>>>(
        y1, w2c, b2, sums1, g1, be1, invM, nullptr,
        y2, sums2, nullptr, nullptr, nullptr, MROWS, 128, 256);

    // 3: L3 (N=64, K=128) NARROW (3 blocks/SM), BN2 affine in-kernel
    bgemm_kernel<1,1,1,0,0><<<dim3(gx, 1), 256>>>(
        y2, w3c, b3, sums2, g2, be2, invM, nullptr,
        y3, sums3, nullptr, nullptr, nullptr, MROWS, 64, 128);

    // 4: xp fused f+b (N=96, K=64), BN3 affine in-kernel
    bgemm_kernel<1,0,0,0,1><<<dim3(gx, 2), 256>>>(
        y3, wifc, bih_f, sums3, g3, be3, invM, nullptr,
        xpf, nullptr, wibc, bih_b, xpb, MROWS, 96, 64);

    // 5: GRU recurrence (frozen R11/R13 form)
    gru_kernel<<<dim3(BB, 2), 32>>>(xpf, xpb, Whh_f, bhh_f, Whh_b, bhh_b, gru);

    // 6: attention scores (N=32, K=64, NARROW+SCORE, 3 blocks/SM)
    bgemm_kernel<0,0,1,1,0><<<dim3(gx, 1), 256>>>(
        gru, wa1c, ba1, nullptr, nullptr, nullptr, 0.f, Wa2,
        scores, nullptr, nullptr, nullptr, nullptr, MROWS, 32, 64);

    // 7: softmax + pooling
    attn_kernel<<<BB, 256>>>(gru, scores, pooled);

    // 8: classifier
    cls_kernel<<<1, 128>>>(pooled, Wc1, bc1, gc, bec, Wc2, bc2, out);
}

// round 16
// speedup vs baseline: 1.0986x; 1.0548x over previous
#include <cuda_runtime.h>
#include <cuda_bf16.h>
#include <stdint.h>
#include <math.h>

// Problem constants
#define BB 128
#define TT 2048
#define FF 80
#define NCLS 10
#define HH 32
#define MROWS (BB*TT)          // 262144
#define EPSBN 1e-5f

typedef unsigned long long ull;

// ---------------- scratch (static __device__ arrays; no allocation) -------
__device__ float g_y1[(size_t)MROWS * 256];
__device__ float g_y2[(size_t)MROWS * 128];
__device__ float g_y3[(size_t)MROWS * 64];
__device__ float g_xpf[(size_t)MROWS * 96];
__device__ float g_xpb[(size_t)MROWS * 96];
__device__ float g_gru[(size_t)MROWS * 64];
__device__ float g_scores[(size_t)MROWS];
__device__ float g_pooled[BB * 64];
__device__ float g_sums1[512];
__device__ float g_sums2[256];
__device__ float g_sums3[128];
// pre-converted weights: uint2 {hi-bf16x2, lo-bf16x2} per k-pair
__device__ uint2 g_w1c[256 * 40];
__device__ uint2 g_w2c[128 * 128];
__device__ uint2 g_w3c[64 * 64];
__device__ uint2 g_wifc[96 * 32];
__device__ uint2 g_wibc[96 * 32];
__device__ uint2 g_wa1c[32 * 32];

// ---------------- helpers ----------------------------------------------------
__device__ __forceinline__ uint32_t pack_bf2(float x, float y) {
    unsigned short h0 = __bfloat16_as_ushort(__float2bfloat16_rn(x));
    unsigned short h1 = __bfloat16_as_ushort(__float2bfloat16_rn(y));
    return (uint32_t)h0 | ((uint32_t)h1 << 16);
}

// truncation hi/lo split: hi = top16 bits (exact residual), lo = bf16(v - hi)
__device__ __forceinline__ void split2(float2 v, uint32_t& hi, uint32_t& lo) {
    uint32_t bx = __float_as_uint(v.x) & 0xffff0000u;
    uint32_t by = __float_as_uint(v.y) & 0xffff0000u;
    hi = (bx >> 16) | by;
    lo = pack_bf2(v.x - __uint_as_float(bx), v.y - __uint_as_float(by));
}

__device__ __forceinline__ void mma_bf16(float* c, const uint32_t* a, const uint32_t* b) {
    asm volatile(
        "mma.sync.aligned.m16n8k16.row.col.f32.bf16.bf16.f32 "
        "{%0,%1,%2,%3}, {%4,%5,%6,%7}, {%8,%9}, {%0,%1,%2,%3};"
        : "+f"(c[0]), "+f"(c[1]), "+f"(c[2]), "+f"(c[3])
        : "r"(a[0]), "r"(a[1]), "r"(a[2]), "r"(a[3]), "r"(b[0]), "r"(b[1]));
}

__device__ __forceinline__ void packf2(ull& d, float lo, float hi) {
    asm("mov.b64 %0, {%1, %2};" : "=l"(d) : "f"(lo), "f"(hi));
}
__device__ __forceinline__ float sumf2(ull v) {
    float lo, hi;
    asm("mov.b64 {%0, %1}, %2;" : "=f"(lo), "=f"(hi) : "l"(v));
    return lo + hi;
}
__device__ __forceinline__ void fma2(ull& d, ull a, ull b) {
    asm("fma.rn.f32x2 %0, %1, %2, %0;" : "+l"(d) : "l"(a), "l"(b));
}
__device__ __forceinline__ float tanh_ap(float x) {
    float y;
    asm("tanh.approx.f32 %0, %1;" : "=f"(y) : "f"(x));
    return y;
}
__device__ __forceinline__ float sigmoid_ap(float x) {
    return fmaf(tanh_ap(0.5f * x), 0.5f, 0.5f);
}

__device__ __forceinline__ uint2 conv_pair(float2 v) {
    uint32_t hi, lo;
    split2(v, hi, lo);
    return make_uint2(hi, lo);
}

// ---------------- prep: zero stats + convert all weights (one launch) -------
#define NP1 10240
#define NP2 16384
#define NP3 4096
#define NPF 3072
#define NPB 3072
#define NPA 1024
#define NPTOT (NP1+NP2+NP3+NPF+NPB+NPA)   // 37888

__global__ void prep_kernel(
    const float* __restrict__ W1, const float* __restrict__ W2,
    const float* __restrict__ W3, const float* __restrict__ Wif,
    const float* __restrict__ Wib, const float* __restrict__ Wa1,
    uint2* w1c, uint2* w2c, uint2* w3c, uint2* wifc, uint2* wibc, uint2* wa1c,
    float* s1, float* s2, float* s3)
{
    int tid = threadIdx.x;
    if (blockIdx.x == 0) {
        if (tid < 512) s1[tid] = 0.f;
        if (tid < 256) s2[tid] = 0.f;
        if (tid < 128) s3[tid] = 0.f;
    }
    for (int p = blockIdx.x * 256 + tid; p < NPTOT; p += gridDim.x * 256) {
        int q = p;
        if (q < NP1) { w1c[q] = conv_pair(((const float2*)W1)[q]); continue; }
        q -= NP1;
        if (q < NP2) { w2c[q] = conv_pair(((const float2*)W2)[q]); continue; }
        q -= NP2;
        if (q < NP3) { w3c[q] = conv_pair(((const float2*)W3)[q]); continue; }
        q -= NP3;
        if (q < NPF) { wifc[q] = conv_pair(((const float2*)Wif)[q]); continue; }
        q -= NPF;
        if (q < NPB) { wibc[q] = conv_pair(((const float2*)Wib)[q]); continue; }
        q -= NPB;
        wa1c[q] = conv_pair(((const float2*)Wa1)[q]);
    }
}

// =====================================================================
// BGEMM (tensor-core, bf16 hi/lo split): C = f(A) @ W^T + bias
// Fragment-owner staging. B hi/lo INTERLEAVED: sB[..][4]={hi_a,hi_b,lo_a,lo_b}
// -> 1 STS.128 + 1 LDS.128 per (nt,warp) instead of 2+2 narrower ops.
// =====================================================================
template<int DO_T, int DO_STATS, int NARROW, int DO_SCORE, int DUAL>
__global__ __launch_bounds__(256, 2 + NARROW) void bgemm_kernel(
    const float* __restrict__ A, const uint2* __restrict__ Whl0,
    const float* __restrict__ bias0,
    const float* __restrict__ stats, const float* __restrict__ gamma,
    const float* __restrict__ beta, float invM,
    const float* __restrict__ wa2,
    float* __restrict__ C0, float* __restrict__ sums,
    const uint2* __restrict__ Whl1, const float* __restrict__ bias1,
    float* __restrict__ C1,
    int M, int N, int K)
{
    __shared__ __align__(16) uint32_t sAh[2][8][32][4];
    __shared__ __align__(16) uint32_t sAl[2][8][32][4];
    __shared__ __align__(16) uint32_t sB[2][16][32][4];   // {hi_a,hi_b,lo_a,lo_b}
    __shared__ float s_sum[128], s_sq[128];
    __shared__ __align__(8) float s_scale[256], s_shift[256];

    const int tid = threadIdx.x;
    const int lane = tid & 31;
    const int wid = tid >> 5;
    const int wm = NARROW ? wid : (wid & 3);
    const int wn = NARROW ? 0 : (wid >> 2);
    const int MT = NARROW ? 1 : 2;
    const int NT = DO_SCORE ? 4 : 8;
    const int bm0 = blockIdx.x * 128;
    const int bn0 = DUAL ? 0 : blockIdx.y * 128;
    const int l4 = lane >> 2;
    const int ln = lane & 3;

    const uint2* Whl = (DUAL && blockIdx.y) ? Whl1 : Whl0;
    const float* bias = (DUAL && blockIdx.y) ? bias1 : bias0;
    float* C = (DUAL && blockIdx.y) ? C1 : C0;

    if (DO_STATS && tid < 128) { s_sum[tid] = 0.f; s_sq[tid] = 0.f; }
    if (DO_T && tid < K) {
        float m = stats[tid] * invM;
        float v = stats[K + tid] * invM - m * m;
        float sc = gamma[tid] * rsqrtf(v + EPSBN);
        s_scale[tid] = sc;
        s_shift[tid] = beta[tid] - m * sc;
    }
    __syncthreads();

    // ---- staging ownership ----
    const int K2 = K >> 1;
    const size_t rA = (size_t)(bm0 + wid * 16 + l4);
    const float2* Ap0 = (const float2*)A + rA * K2 + ln;
    const float2* Ap1 = Ap0 + (size_t)8 * K2;

    const int NSLOT = NARROW ? 1 : 2;
    int ntB[2];
    const uint2* Wp[2];
    bool wokB[2];
#pragma unroll
    for (int s = 0; s < NSLOT; s++) {
        ntB[s] = NARROW ? wid : (wid * 2 + s);
        int n = bn0 + ntB[s] * 8 + l4;
        wokB[s] = (n < N);
        Wp[s] = wokB[s] ? (Whl + (size_t)n * K2 + ln) : Whl;
    }

    float acc[NARROW ? 1 : 2][DO_SCORE ? 4 : 8][4];
#pragma unroll
    for (int mt = 0; mt < MT; mt++)
#pragma unroll
        for (int nt = 0; nt < NT; nt++)
#pragma unroll
            for (int q = 0; q < 4; q++) acc[mt][nt][q] = 0.f;

    const int nch = K >> 4;

    float2 a00, a10, a01, a11;
    uint2 wb[2][2];

    // ---- load chunk 0 into regs ----
    {
        a00 = Ap0[0];  a01 = Ap0[4];
        a10 = Ap1[0];  a11 = Ap1[4];
        if (DO_T) {
            float2 sc0 = ((const float2*)s_scale)[ln];
            float2 sh0 = ((const float2*)s_shift)[ln];
            float2 sc1 = ((const float2*)s_scale)[ln + 4];
            float2 sh1 = ((const float2*)s_shift)[ln + 4];
            a00.x = fmaxf(fmaf(a00.x, sc0.x, sh0.x), 0.f);
            a00.y = fmaxf(fmaf(a00.y, sc0.y, sh0.y), 0.f);
            a10.x = fmaxf(fmaf(a10.x, sc0.x, sh0.x), 0.f);
            a10.y = fmaxf(fmaf(a10.y, sc0.y, sh0.y), 0.f);
            a01.x = fmaxf(fmaf(a01.x, sc1.x, sh1.x), 0.f);
            a01.y = fmaxf(fmaf(a01.y, sc1.y, sh1.y), 0.f);
            a11.x = fmaxf(fmaf(a11.x, sc1.x, sh1.x), 0.f);
            a11.y = fmaxf(fmaf(a11.y, sc1.y, sh1.y), 0.f);
        }
#pragma unroll
        for (int s = 0; s < NSLOT; s++) {
            wb[s][0] = wokB[s] ? Wp[s][0] : make_uint2(0u, 0u);
            wb[s][1] = wokB[s] ? Wp[s][4] : make_uint2(0u, 0u);
        }
    }
    {
        uint32_t h0, l0, h1, l1, h2, l2, h3, l3;
        split2(a00, h0, l0); split2(a10, h1, l1);
        split2(a01, h2, l2); split2(a11, h3, l3);
        *(uint4*)&sAh[0][wid][lane][0] = make_uint4(h0, h1, h2, h3);
        *(uint4*)&sAl[0][wid][lane][0] = make_uint4(l0, l1, l2, l3);
#pragma unroll
        for (int s = 0; s < NSLOT; s++)
            *(uint4*)&sB[0][ntB[s]][lane][0] =
                make_uint4(wb[s][0].x, wb[s][1].x, wb[s][0].y, wb[s][1].y);
    }
    __syncthreads();

    for (int s = 0; s < nch; s++) {
        const int cur = s & 1;
        const int kq2 = (s + 1) << 3;

        if (s + 1 < nch) {
            a00 = Ap0[kq2];     a01 = Ap0[kq2 + 4];
            a10 = Ap1[kq2];     a11 = Ap1[kq2 + 4];
            if (DO_T) {
                float2 sc0 = ((const float2*)s_scale)[kq2 + ln];
                float2 sh0 = ((const float2*)s_shift)[kq2 + ln];
                float2 sc1 = ((const float2*)s_scale)[kq2 + ln + 4];
                float2 sh1 = ((const float2*)s_shift)[kq2 + ln + 4];
                a00.x = fmaxf(fmaf(a00.x, sc0.x, sh0.x), 0.f);
                a00.y = fmaxf(fmaf(a00.y, sc0.y, sh0.y), 0.f);
                a10.x = fmaxf(fmaf(a10.x, sc0.x, sh0.x), 0.f);
                a10.y = fmaxf(fmaf(a10.y, sc0.y, sh0.y), 0.f);
                a01.x = fmaxf(fmaf(a01.x, sc1.x, sh1.x), 0.f);
                a01.y = fmaxf(fmaf(a01.y, sc1.y, sh1.y), 0.f);
                a11.x = fmaxf(fmaf(a11.x, sc1.x, sh1.x), 0.f);
                a11.y = fmaxf(fmaf(a11.y, sc1.y, sh1.y), 0.f);
            }
#pragma unroll
            for (int t = 0; t < NSLOT; t++) {
                wb[t][0] = wokB[t] ? Wp[t][kq2] : make_uint2(0u, 0u);
                wb[t][1] = wokB[t] ? Wp[t][kq2 + 4] : make_uint2(0u, 0u);
            }
        }

        // ---- MMA on current buffer ----
        {
            uint32_t ah[2][4], al[2][4];
#pragma unroll
            for (int mt = 0; mt < MT; mt++) {
                const int mtile = NARROW ? wm : (wm * 2 + mt);
                uint4 t0 = *(const uint4*)&sAh[cur][mtile][lane][0];
                ah[mt][0] = t0.x; ah[mt][1] = t0.y; ah[mt][2] = t0.z; ah[mt][3] = t0.w;
                uint4 t1 = *(const uint4*)&sAl[cur][mtile][lane][0];
                al[mt][0] = t1.x; al[mt][1] = t1.y; al[mt][2] = t1.z; al[mt][3] = t1.w;
            }
#pragma unroll
            for (int nt = 0; nt < NT; nt++) {
                uint4 q4 = *(const uint4*)&sB[cur][wn * 8 + nt][lane][0];
                uint32_t bh[2] = {q4.x, q4.y};
                uint32_t bl[2] = {q4.z, q4.w};
#pragma unroll
                for (int mt = 0; mt < MT; mt++) {
                    mma_bf16(acc[mt][nt], ah[mt], bh);
                    mma_bf16(acc[mt][nt], ah[mt], bl);
                    mma_bf16(acc[mt][nt], al[mt], bh);
                }
            }
        }

        if (s + 1 < nch) {
            const int nxt = cur ^ 1;
            uint32_t h0, l0, h1, l1, h2, l2, h3, l3;
            split2(a00, h0, l0); split2(a10, h1, l1);
            split2(a01, h2, l2); split2(a11, h3, l3);
            *(uint4*)&sAh[nxt][wid][lane][0] = make_uint4(h0, h1, h2, h3);
            *(uint4*)&sAl[nxt][wid][lane][0] = make_uint4(l0, l1, l2, l3);
#pragma unroll
            for (int t = 0; t < NSLOT; t++)
                *(uint4*)&sB[nxt][ntB[t]][lane][0] =
                    make_uint4(wb[t][0].x, wb[t][1].x, wb[t][0].y, wb[t][1].y);
            __syncthreads();
        }
    }

    if (DO_SCORE) {
        float s0 = 0.f, s1 = 0.f;
#pragma unroll
        for (int nt = 0; nt < 4; nt++) {
            const int col = nt * 8 + ln * 2;
            float b0 = bias[col], b1 = bias[col + 1];
            float w0 = wa2[col], w1 = wa2[col + 1];
            s0 += tanhf(acc[0][nt][0] + b0) * w0 + tanhf(acc[0][nt][1] + b1) * w1;
            s1 += tanhf(acc[0][nt][2] + b0) * w0 + tanhf(acc[0][nt][3] + b1) * w1;
        }
        s0 += __shfl_xor_sync(0xffffffffu, s0, 1);
        s0 += __shfl_xor_sync(0xffffffffu, s0, 2);
        s1 += __shfl_xor_sync(0xffffffffu, s1, 1);
        s1 += __shfl_xor_sync(0xffffffffu, s1, 2);
        if (ln == 0) {
            C[bm0 + wm * 16 + l4]     = s0;
            C[bm0 + wm * 16 + l4 + 8] = s1;
        }
        return;
    }

    // ---- normal epilogue ----
#pragma unroll
    for (int nt = 0; nt < NT; nt++) {
        const int colb = wn * 64 + nt * 8 + ln * 2;
        const int col = bn0 + colb;
        const bool ok = (col < N);
        float b0 = ok ? bias[col] : 0.f;
        float b1 = ok ? bias[col + 1] : 0.f;
        float cs0 = 0.f, cs1 = 0.f, cq0 = 0.f, cq1 = 0.f;
#pragma unroll
        for (int mt = 0; mt < MT; mt++) {
            float c0 = acc[mt][nt][0] + b0;
            float c1 = acc[mt][nt][1] + b1;
            float c2 = acc[mt][nt][2] + b0;
            float c3 = acc[mt][nt][3] + b1;
            const int row = bm0 + (NARROW ? wm * 16 : wm * 32 + mt * 16) + l4;
            if (ok) {
                *(float2*)(C + (size_t)row * N + col)       = make_float2(c0, c1);
                *(float2*)(C + (size_t)(row + 8) * N + col) = make_float2(c2, c3);
            }
            if (DO_STATS) {
                cs0 += c0 + c2; cs1 += c1 + c3;
                cq0 += c0 * c0 + c2 * c2; cq1 += c1 * c1 + c3 * c3;
            }
        }
        if (DO_STATS) {
#pragma unroll
            for (int o = 4; o < 32; o <<= 1) {
                cs0 += __shfl_xor_sync(0xffffffffu, cs0, o);
                cs1 += __shfl_xor_sync(0xffffffffu, cs1, o);
                cq0 += __shfl_xor_sync(0xffffffffu, cq0, o);
                cq1 += __shfl_xor_sync(0xffffffffu, cq1, o);
            }
            if (l4 == 0) {
                atomicAdd(&s_sum[colb], cs0);
                atomicAdd(&s_sum[colb + 1], cs1);
                atomicAdd(&s_sq[colb], cq0);
                atomicAdd(&s_sq[colb + 1], cq1);
            }
        }
    }

    if (DO_STATS) {
        __syncthreads();
        if (tid < 128) {
            int n = bn0 + tid;
            if (n < N) {
                atomicAdd(&sums[n],     s_sum[tid]);
                atomicAdd(&sums[N + n], s_sq[tid]);
            }
        }
    }
}

// ---------------- GRU recurrence (one warp per (batch, direction)) ----------
// R11 geometry (256 single-warp blocks) with smem double-buffered h broadcast:
// replaces 32 SHFL + 16 packf2 per step with 1 STS + 1 syncwarp + 16
// broadcast LDS.64 (pre-paired for fma2). depth-4 static xp prefetch,
// tanh.approx nonlinearities.
__global__ __launch_bounds__(32) void gru_kernel(
    const float* __restrict__ xp_f, const float* __restrict__ xp_b,
    const float* __restrict__ Whh_f, const float* __restrict__ bhh_f,
    const float* __restrict__ Whh_b, const float* __restrict__ bhh_b,
    float* __restrict__ gru_out)
{
    __shared__ __align__(8) float sh[2][32];

    int b = blockIdx.x;
    int dir = blockIdx.y;
    int j = threadIdx.x;

    const float* xp  = dir ? xp_b  : xp_f;
    const float* Whh = dir ? Whh_b : Whh_f;
    const float* bhh = dir ? bhh_b : bhh_f;

    ull Wr2[16], Wz2[16], Wn2[16];
#pragma unroll
    for (int k2 = 0; k2 < 16; k2++) {
        packf2(Wr2[k2], Whh[j * 32 + 2 * k2],        Whh[j * 32 + 2 * k2 + 1]);
        packf2(Wz2[k2], Whh[(32 + j) * 32 + 2 * k2], Whh[(32 + j) * 32 + 2 * k2 + 1]);
        packf2(Wn2[k2], Whh[(64 + j) * 32 + 2 * k2], Whh[(64 + j) * 32 + 2 * k2 + 1]);
    }
    float br = bhh[j], bz = bhh[32 + j], bnn = bhh[64 + j];

    float h = 0.f;
    sh[0][j] = 0.f;
    __syncwarp();
    int ph = 0;

    const int st = dir ? -96 : 96;
    int tcur = dir ? (TT - 1) : 0;
    const float* cur = xp + (size_t)b * TT * 96 + (size_t)tcur * 96;
    const float* pf = cur + 4 * st;
    float* outp = gru_out + ((size_t)b * TT + tcur) * 64 + dir * 32 + j;
    const long ost = dir ? -64 : 64;

    float fr[4], fz[4], fn[4];
#pragma unroll
    for (int q = 0; q < 4; q++) {
        const float* p = cur + q * st;
        fr[q] = p[j]; fz[q] = p[32 + j]; fn[q] = p[64 + j];
    }

    for (int it = 0; it < TT; it += 4) {
        float nfr[4], nfz[4], nfn[4];
        const bool more = (it + 4 < TT);
        if (more) {
#pragma unroll
            for (int q = 0; q < 4; q++) {
                const float* p = pf + q * st;
                nfr[q] = p[j]; nfz[q] = p[32 + j]; nfn[q] = p[64 + j];
            }
        }
        pf += 4 * st;

#pragma unroll
        for (int u = 0; u < 4; u++) {
            ull ra = 0ull, rb = 0ull;
            ull za = 0ull, zb = 0ull;
            ull na = 0ull, nb = 0ull;
            const float* hb = &sh[ph][0];
#pragma unroll
            for (int k2 = 0; k2 < 16; k2++) {
                ull hp = *(const ull*)(hb + 2 * k2);     // broadcast LDS.64
                if (k2 & 1) {
                    fma2(rb, Wr2[k2], hp);
                    fma2(zb, Wz2[k2], hp);
                    fma2(nb, Wn2[k2], hp);
                } else {
                    fma2(ra, Wr2[k2], hp);
                    fma2(za, Wz2[k2], hp);
                    fma2(na, Wn2[k2], hp);
                }
            }
            float accr = br + sumf2(ra) + sumf2(rb);
            float accz = bz + sumf2(za) + sumf2(zb);
            float accn = bnn + sumf2(na) + sumf2(nb);
            float r = sigmoid_ap(fr[u] + accr);
            float z = sigmoid_ap(fz[u] + accz);
            float n = tanh_ap(fmaf(r, accn, fn[u]));
            h = fmaf(z, h - n, n);
            sh[ph ^ 1][j] = h;
            __syncwarp();
            ph ^= 1;
            *outp = h;
            outp += ost;
        }
#pragma unroll
        for (int q = 0; q < 4; q++) { fr[q] = nfr[q]; fz[q] = nfz[q]; fn[q] = nfn[q]; }
    }
}

// ---------------- softmax + pooling (scores precomputed) --------------------
__global__ __launch_bounds__(256) void attn_kernel(
    const float* __restrict__ gru,
    const float* __restrict__ scores,
    float* __restrict__ pooled)
{
    __shared__ float s_scores[TT];
    __shared__ float s_red[8];
    __shared__ float s_bcast[2];
    __shared__ float s_pool[4][64];

    int b = blockIdx.x;
    int tid = threadIdx.x;
    int lane = tid & 31;
    int w = tid >> 5;

    const float* sb = scores + (size_t)b * TT;
    for (int t = tid; t < TT; t += 256) s_scores[t] = sb[t];
    __syncthreads();

    float m = -1e30f;
    for (int t = tid; t < TT; t += 256) m = fmaxf(m, s_scores[t]);
#pragma unroll
    for (int o = 16; o; o >>= 1) m = fmaxf(m, __shfl_xor_sync(0xffffffffu, m, o));
    if (lane == 0) s_red[w] = m;
    __syncthreads();
    if (tid == 0) {
        float mm = s_red[0];
#pragma unroll
        for (int i = 1; i < 8; i++) mm = fmaxf(mm, s_red[i]);
        s_bcast[0] = mm;
    }
    __syncthreads();
    m = s_bcast[0];

    float sum = 0.f;
    for (int t = tid; t < TT; t += 256) {
        float e = __expf(s_scores[t] - m);
        s_scores[t] = e;
        sum += e;
    }
#pragma unroll
    for (int o = 16; o; o >>= 1) sum += __shfl_xor_sync(0xffffffffu, sum, o);
    if (lane == 0) s_red[w] = sum;
    __syncthreads();
    if (tid == 0) {
        float ss = 0.f;
#pragma unroll
        for (int i = 0; i < 8; i++) ss += s_red[i];
        s_bcast[1] = ss;
    }
    __syncthreads();
    float sumexp = s_bcast[1];

    const float* gb = gru + (size_t)b * TT * 64;
    int c = tid & 63;
    int grp = tid >> 6;
    float acc = 0.f;
    for (int t = grp; t < TT; t += 4) acc += s_scores[t] * gb[(size_t)t * 64 + c];
    s_pool[grp][c] = acc;
    __syncthreads();
    if (tid < 64) {
        float tot = s_pool[0][tid] + s_pool[1][tid] + s_pool[2][tid] + s_pool[3][tid];
        pooled[b * 64 + tid] = tot / sumexp;
    }
}

// ---------------- classifier -------------------------------------------------
__global__ __launch_bounds__(128) void cls_kernel(
    const float* __restrict__ pooled,
    const float* __restrict__ Wc1, const float* __restrict__ bc1,
    const float* __restrict__ gc, const float* __restrict__ bec,
    const float* __restrict__ Wc2, const float* __restrict__ bc2,
    float* __restrict__ out)
{
    __shared__ float s_sum[32], s_sq[32], s_scale[32], s_shift[32];
    int r = threadIdx.x;
    if (r < 32) { s_sum[r] = 0.f; s_sq[r] = 0.f; }
    __syncthreads();

    float x[64];
#pragma unroll
    for (int k = 0; k < 64; k++) x[k] = pooled[r * 64 + k];

    float q[32];
#pragma unroll
    for (int u = 0; u < 32; u++) {
        float a = bc1[u];
#pragma unroll
        for (int k = 0; k < 64; k++) a += Wc1[u * 64 + k] * x[k];
        q[u] = a;
        atomicAdd(&s_sum[u], a);
        atomicAdd(&s_sq[u], a * a);
    }
    __syncthreads();
    if (r < 32) {
        float m = s_sum[r] * (1.f / 128.f);
        float v = s_sq[r] * (1.f / 128.f) - m * m;
        float sc = gc[r] * rsqrtf(v + EPSBN);
        s_scale[r] = sc;
        s_shift[r] = bec[r] - m * sc;
    }
    __syncthreads();

    float qn[32];
#pragma unroll
    for (int u = 0; u < 32; u++) {
        float t = q[u] * s_scale[u] + s_shift[u];
        qn[u] = t > 0.f ? t : 0.f;
    }
#pragma unroll
    for (int c = 0; c < NCLS; c++) {
        float a = bc2[c];
#pragma unroll
        for (int k = 0; k < 32; k++) a += Wc2[c * 32 + k] * qn[k];
        out[r * NCLS + c] = a;
    }
}

// ---------------- launch ----------------------------------------------------
extern "C" void kernel_launch(void* const* d_in, const int* in_sizes, int n_in,
                              void* d_out, int out_size)
{
    (void)in_sizes; (void)n_in; (void)out_size;

    const float* x     = (const float*)d_in[0];
    const float* W1    = (const float*)d_in[1];
    const float* b1    = (const float*)d_in[2];
    const float* g1    = (const float*)d_in[3];
    const float* be1   = (const float*)d_in[4];
    const float* W2    = (const float*)d_in[5];
    const float* b2    = (const float*)d_in[6];
    const float* g2    = (const float*)d_in[7];
    const float* be2   = (const float*)d_in[8];
    const float* W3    = (const float*)d_in[9];
    const float* b3    = (const float*)d_in[10];
    const float* g3    = (const float*)d_in[11];
    const float* be3   = (const float*)d_in[12];
    const float* Wih_f = (const float*)d_in[13];
    const float* Whh_f = (const float*)d_in[14];
    const float* bih_f = (const float*)d_in[15];
    const float* bhh_f = (const float*)d_in[16];
    const float* Wih_b = (const float*)d_in[17];
    const float* Whh_b = (const float*)d_in[18];
    const float* bih_b = (const float*)d_in[19];
    const float* bhh_b = (const float*)d_in[20];
    const float* Wa1   = (const float*)d_in[21];
    const float* ba1   = (const float*)d_in[22];
    const float* Wa2   = (const float*)d_in[23];
    const float* ba2   = (const float*)d_in[24];  (void)ba2;  // softmax-invariant
    const float* Wc1   = (const float*)d_in[25];
    const float* bc1   = (const float*)d_in[26];
    const float* gc    = (const float*)d_in[27];
    const float* bec   = (const float*)d_in[28];
    const float* Wc2   = (const float*)d_in[29];
    const float* bc2   = (const float*)d_in[30];
    float* out = (float*)d_out;

    float *y1, *y2, *y3, *xpf, *xpb, *gru, *scores, *pooled;
    float *sums1, *sums2, *sums3;
    uint2 *w1c, *w2c, *w3c, *wifc, *wibc, *wa1c;
    cudaGetSymbolAddress((void**)&y1, g_y1);
    cudaGetSymbolAddress((void**)&y2, g_y2);
    cudaGetSymbolAddress((void**)&y3, g_y3);
    cudaGetSymbolAddress((void**)&xpf, g_xpf);
    cudaGetSymbolAddress((void**)&xpb, g_xpb);
    cudaGetSymbolAddress((void**)&gru, g_gru);
    cudaGetSymbolAddress((void**)&scores, g_scores);
    cudaGetSymbolAddress((void**)&pooled, g_pooled);
    cudaGetSymbolAddress((void**)&sums1, g_sums1);
    cudaGetSymbolAddress((void**)&sums2, g_sums2);
    cudaGetSymbolAddress((void**)&sums3, g_sums3);
    cudaGetSymbolAddress((void**)&w1c, g_w1c);
    cudaGetSymbolAddress((void**)&w2c, g_w2c);
    cudaGetSymbolAddress((void**)&w3c, g_w3c);
    cudaGetSymbolAddress((void**)&wifc, g_wifc);
    cudaGetSymbolAddress((void**)&wibc, g_wibc);
    cudaGetSymbolAddress((void**)&wa1c, g_wa1c);

    const float invM = 1.f / (float)MROWS;
    const int gx = MROWS / 128;

    // 0: prep (zero stats + all weight conversions)
    prep_kernel<<<148, 256>>>(W1, W2, W3, Wih_f, Wih_b, Wa1,
                              w1c, w2c, w3c, wifc, wibc, wa1c,
                              sums1, sums2, sums3);

    // 1: L1 (N=256, K=80) + stats
    bgemm_kernel<0,1,0,0,0><<<dim3(gx, 2), 256>>>(
        x, w1c, b1, nullptr, nullptr, nullptr, 0.f, nullptr,
        y1, sums1, nullptr, nullptr, nullptr, MROWS, 256, FF);

    // 2: L2 (N=128, K=256), BN1 affine in-kernel
    bgemm_kernel<1,1,0,0,0><<<dim3(gx, 1), 256>>>(
        y1, w2c, b2, sums1, g1, be1, invM, nullptr,
        y2, sums2, nullptr, nullptr, nullptr, MROWS, 128, 256);

    // 3: L3 (N=64, K=128) NARROW, BN2 affine in-kernel
    bgemm_kernel<1,1,1,0,0><<<dim3(gx, 1), 256>>>(
        y2, w3c, b3, sums2, g2, be2, invM, nullptr,
        y3, sums3, nullptr, nullptr, nullptr, MROWS, 64, 128);

    // 4: xp fused f+b (N=96, K=64), BN3 affine in-kernel
    bgemm_kernel<1,0,0,0,1><<<dim3(gx, 2), 256>>>(
        y3, wifc, bih_f, sums3, g3, be3, invM, nullptr,
        xpf, nullptr, wibc, bih_b, xpb, MROWS, 96, 64);

    // 5: GRU recurrence (smem h-broadcast, 256 single-warp blocks)
    gru_kernel<<<dim3(BB, 2), 32>>>(xpf, xpb, Whh_f, bhh_f, Whh_b, bhh_b, gru);

    // 6: attention scores (N=32, K=64, NARROW+SCORE)
    bgemm_kernel<0,0,1,1,0><<<dim3(gx, 1), 256>>>(
        gru, wa1c, ba1, nullptr, nullptr, nullptr, 0.f, Wa2,
        scores, nullptr, nullptr, nullptr, nullptr, MROWS, 32, 64);

    // 7: softmax + pooling
    attn_kernel<<<BB, 256>>>(gru, scores, pooled);

    // 8: classifier
    cls_kernel<<<1, 128>>>(pooled, Wc1, bc1, gc, bec, Wc2, bc2, out);
}